// round 1
// baseline (speedup 1.0000x reference)
#include <cuda_runtime.h>
#include <cuda_bf16.h>

// LocalDynamicGraph edge features:
//   out[b,n,c,k]    = x[b, idx[b,n,k], c] - x[b,n,c]   for c in [0,64)
//   out[b,n,64+c,k] = x[b,n,c]                          for c in [0,64)
// Shapes: B=8, N=16384, C=64, K=20. Output (B,N,128,20) fp32 = 1.342 GB.
// HBM-write-bound; x (32 MB) lives in L2 so gathers are L2 hits.

#define BDIM   8
#define NPTS   16384
#define CH     64
#define KNB    20
#define OUTPP  (2 * CH * KNB)   // 2560 floats per point
#define THREADS 128

// Runtime flag: 1 if idx buffer is genuinely int64, 0 if it is int32.
__device__ int g_idx_is64;

__global__ void detect_idx_dtype_kernel(const long long* __restrict__ p) {
    // If the buffer is really int64, every element is a valid index in
    // [0, 16384). If it is int32 data aliased as int64, the high 32 bits of
    // (almost) every 8-byte word hold a random index >= 1, making the value
    // >= 2^32. Probe 8 words; false positive prob ~ 16384^-8.
    int is64 = 1;
    #pragma unroll
    for (int i = 0; i < 8; i++) {
        long long v = p[i];
        if (v < 0 || v >= NPTS) is64 = 0;
    }
    g_idx_is64 = is64;
}

__global__ __launch_bounds__(THREADS)
void edge_feature_kernel(const float* __restrict__ x,
                         const void* __restrict__ idx_raw,
                         float* __restrict__ out) {
    const int pt = blockIdx.x;            // 0 .. B*N-1
    const int b  = pt >> 14;              // N = 16384
    const int n  = pt & (NPTS - 1);
    const int t  = threadIdx.x;

    __shared__ float s_center[CH];
    __shared__ float s_nbr[KNB][CH + 1];  // stride 65: conflict-free transposed reads
    __shared__ int   s_nidx[KNB];

    const float* xb = x + (size_t)b * NPTS * CH;

    // --- stage center row + neighbor indices ---
    if (t < CH) {
        s_center[t] = xb[(size_t)n * CH + t];
    }
    if (t >= CH && t < CH + KNB) {
        const int j = t - CH;
        const int is64 = g_idx_is64;      // uniform; L1/L2 broadcast
        long long v;
        if (is64) v = ((const long long*)idx_raw)[(size_t)pt * KNB + j];
        else      v = ((const int*)idx_raw)[(size_t)pt * KNB + j];
        s_nidx[j] = (int)v;
    }
    __syncthreads();

    // --- gather 20 neighbor rows (20*64 floats) into smem, coalesced ---
    // flat index f = t + i*128; row = f/64 (uniform per half-warp), col = f%64.
    // Each 64-thread group reads one contiguous 256B row of x (L2 hit).
    #pragma unroll
    for (int i = 0; i < (KNB * CH) / THREADS; i++) {   // 10 iterations
        const int f = t + i * THREADS;
        const int r = f >> 6;
        const int c = f & (CH - 1);
        s_nbr[r][c] = xb[(size_t)s_nidx[r] * CH + c];
    }
    __syncthreads();

    // --- emit 2560 floats = 640 float4 (K=20 -> 5 float4 per channel row) ---
    float4* outp = (float4*)(out + (size_t)pt * OUTPP);
    #pragma unroll
    for (int i = 0; i < 5; i++) {
        const int j4 = t + i * THREADS;   // 0..639, consecutive across warp -> coalesced
        const int c2 = j4 / 5;
        const int kk = (j4 - c2 * 5) * 4;
        float4 v;
        if (c2 < CH) {
            const float ctr = s_center[c2];
            v.x = s_nbr[kk + 0][c2] - ctr;
            v.y = s_nbr[kk + 1][c2] - ctr;
            v.z = s_nbr[kk + 2][c2] - ctr;
            v.w = s_nbr[kk + 3][c2] - ctr;
        } else {
            const float ctr = s_center[c2 - CH];
            v = make_float4(ctr, ctr, ctr, ctr);
        }
        outp[j4] = v;
    }
}

extern "C" void kernel_launch(void* const* d_in, const int* in_sizes, int n_in,
                              void* d_out, int out_size) {
    const float* x   = (const float*)d_in[0];
    const void*  idx = d_in[1];
    float*       out = (float*)d_out;

    detect_idx_dtype_kernel<<<1, 1>>>((const long long*)idx);
    edge_feature_kernel<<<BDIM * NPTS, THREADS>>>(x, idx, out);
}

// round 2
// speedup vs baseline: 1.2596x; 1.2596x over previous
#include <cuda_runtime.h>
#include <cuda_bf16.h>

// LocalDynamicGraph edge features:
//   out[b,n,c,k]    = x[b, idx[b,n,k], c] - x[b,n,c]   for c in [0,64)
//   out[b,n,64+c,k] = x[b,n,c]                          for c in [0,64)
// Shapes: B=8, N=16384, C=64, K=20. Output (B,N,128,20) fp32 = 1.342 GB.
// Write-bound. R1 change: overlap the gather-independent center-broadcast
// half (50% of written bytes) with the gather LDG latency; streaming stores.

#define BDIM   8
#define NPTS   16384
#define CH     64
#define KNB    20
#define OUTPP  (2 * CH * KNB)   // 2560 floats per point
#define THREADS 128

// Runtime flag: 1 if idx buffer is genuinely int64, 0 if it is int32.
__device__ int g_idx_is64;

__global__ void detect_idx_dtype_kernel(const long long* __restrict__ p) {
    // Genuine int64 indices are all in [0, 16384). int32 data aliased as
    // int64 puts a random nonzero index in the high 32 bits of almost every
    // word. Probe 8 words; false-positive prob ~ 16384^-8.
    int is64 = 1;
    #pragma unroll
    for (int i = 0; i < 8; i++) {
        long long v = p[i];
        if (v < 0 || v >= NPTS) is64 = 0;
    }
    g_idx_is64 = is64;
}

__global__ __launch_bounds__(THREADS)
void edge_feature_kernel(const float* __restrict__ x,
                         const void* __restrict__ idx_raw,
                         float* __restrict__ out) {
    const int pt = blockIdx.x;            // 0 .. B*N-1
    const int b  = pt >> 14;              // N = 16384
    const int n  = pt & (NPTS - 1);
    const int t  = threadIdx.x;

    __shared__ float s_center[CH];
    __shared__ float s_nbr[KNB][CH + 1];  // stride 65: conflict-free column reads
    __shared__ int   s_nidx[KNB];

    const float* xb   = x + (size_t)b * NPTS * CH;
    const float* xrow = xb + (size_t)n * CH;

    // --- stage center row + neighbor indices ---
    if (t < CH) {
        s_center[t] = xrow[t];
    } else if (t < CH + KNB) {
        const int j = t - CH;
        long long v;
        if (g_idx_is64) v = ((const long long*)idx_raw)[(size_t)pt * KNB + j];
        else            v = (long long)((const int*)idx_raw)[(size_t)pt * KNB + j];
        s_nidx[j] = (int)v;
    }
    __syncthreads();

    // --- issue all 20-row gathers into registers (MLP = 10 per thread) ---
    float g[10];
    int   rr[10], cc[10];
    #pragma unroll
    for (int i = 0; i < 10; i++) {
        const int f = t + i * THREADS;
        rr[i] = f >> 6;                   // row 0..19 (uniform per 64-thread group)
        cc[i] = f & (CH - 1);
        g[i]  = xb[(size_t)s_nidx[rr[i]] * CH + cc[i]];   // 256B-coalesced, L2 hit
    }

    float4* outp = (float4*)(out + (size_t)pt * OUTPP);

    // --- center-broadcast half: independent of gathers, hides their latency.
    // out[64+c][k] = center[c]; 320 float4 (j4 in [320,640)).
    #pragma unroll
    for (int i = 0; i < 3; i++) {
        const int j4 = 320 + t + i * THREADS;
        if (j4 < 640) {
            const int c  = j4 / 5 - CH;
            const float ctr = __ldg(xrow + c);     // broadcast hit
            __stcs(&outp[j4], make_float4(ctr, ctr, ctr, ctr));
        }
    }

    // --- commit gathered rows to smem, then emit edge half ---
    #pragma unroll
    for (int i = 0; i < 10; i++) s_nbr[rr[i]][cc[i]] = g[i];
    __syncthreads();

    #pragma unroll
    for (int i = 0; i < 3; i++) {
        const int j4 = t + i * THREADS;   // [0,320): out[c][k] = nbr[k][c]-ctr
        if (j4 < 320) {
            const int c2 = j4 / 5;
            const int kk = (j4 - c2 * 5) * 4;
            const float ctr = s_center[c2];
            float4 v;
            v.x = s_nbr[kk + 0][c2] - ctr;
            v.y = s_nbr[kk + 1][c2] - ctr;
            v.z = s_nbr[kk + 2][c2] - ctr;
            v.w = s_nbr[kk + 3][c2] - ctr;
            __stcs(&outp[j4], v);
        }
    }
}

extern "C" void kernel_launch(void* const* d_in, const int* in_sizes, int n_in,
                              void* d_out, int out_size) {
    const float* x   = (const float*)d_in[0];
    const void*  idx = d_in[1];
    float*       out = (float*)d_out;

    detect_idx_dtype_kernel<<<1, 1>>>((const long long*)idx);
    edge_feature_kernel<<<BDIM * NPTS, THREADS>>>(x, idx, out);
}

// round 3
// speedup vs baseline: 1.2906x; 1.0246x over previous
#include <cuda_runtime.h>
#include <cuda_bf16.h>

// LocalDynamicGraph edge features:
//   out[b,n,c,k]    = x[b, idx[b,n,k], c] - x[b,n,c]   for c in [0,64)
//   out[b,n,64+c,k] = x[b,n,c]                          for c in [0,64)
// B=8, N=16384, C=64, K=20. Output (B,N,128,20) fp32 = 1.342 GB, write-bound.
// R2: cut L1/LSU wavefronts (the co-binder at 292/CTA vs 240-cycle DRAM
// budget): subtract center at gather time (fixed c per thread), vectorize
// row-index loads via warp-half row ownership.

#define BDIM    8
#define NPTS    16384
#define CH      64
#define KNB     20
#define OUTPP   (2 * CH * KNB)   // 2560 floats per point
#define THREADS 128
#define PAD     65

// Runtime flag: 1 if idx buffer is genuinely int64, 0 if it is int32.
__device__ int g_idx_is64;

__global__ void detect_idx_dtype_kernel(const long long* __restrict__ p) {
    // Genuine int64 indices all lie in [0, 16384). int32 data aliased as
    // int64 puts a random nonzero index in the high 32 bits of almost every
    // word. Probe 8 words; false-positive prob ~ 16384^-8.
    int is64 = 1;
    #pragma unroll
    for (int i = 0; i < 8; i++) {
        long long v = p[i];
        if (v < 0 || v >= NPTS) is64 = 0;
    }
    g_idx_is64 = is64;
}

__global__ __launch_bounds__(THREADS)
void edge_feature_kernel(const float* __restrict__ x,
                         const void* __restrict__ idx_raw,
                         float* __restrict__ out) {
    const int pt = blockIdx.x;            // 0 .. B*N-1
    const int b  = pt >> 14;              // N = 16384
    const int n  = pt & (NPTS - 1);
    const int t  = threadIdx.x;

    // s_nbr holds (nbr - center), i.e. the edge half, pre-subtracted.
    __shared__ float s_nbr[KNB][PAD];
    __shared__ int   s_nidx[24];          // rows 0..9 at [0..9], 10..19 at [12..21]

    const float* xb   = x + (size_t)b * NPTS * CH;
    const float* xrow = xb + (size_t)n * CH;

    // --- stage neighbor indices (threads 0..19, warp 0) ---
    if (t < KNB) {
        long long v;
        if (g_idx_is64) v = ((const long long*)idx_raw)[(size_t)pt * KNB + t];
        else            v = (long long)((const int*)idx_raw)[(size_t)pt * KNB + t];
        s_nidx[t < 10 ? t : t + 2] = (int)v;   // 16B-aligned bases per half
    }
    __syncthreads();

    // --- per-thread gather assignment: fixed channel, 10 consecutive rows ---
    const int c    = t & (CH - 1);        // 0..63
    const int half = t >> 6;              // warps 0,1 -> rows 0..9; 2,3 -> 10..19
    const float ctr_c = __ldg(xrow + c);  // one center value per thread

    // 10 consecutive row indices via 3 vector LDS (broadcast within groups)
    const int base = half * 12;
    int4 ra = *(const int4*)&s_nidx[base];
    int4 rb = *(const int4*)&s_nidx[base + 4];
    int2 rc = *(const int2*)&s_nidx[base + 8];
    int rows[10] = {ra.x, ra.y, ra.z, ra.w, rb.x, rb.y, rb.z, rb.w, rc.x, rc.y};

    // --- issue all gathers (MLP=10, 256B-coalesced per instruction) ---
    float g[10];
    #pragma unroll
    for (int i = 0; i < 10; i++)
        g[i] = xb[(size_t)rows[i] * CH + c];

    float4* outp = (float4*)(out + (size_t)pt * OUTPP);

    // --- center-broadcast half: independent of gathers, hides LDG latency.
    // out[64+c2][k] = center[c2]; j4 in [320,640).
    #pragma unroll
    for (int i = 0; i < 3; i++) {
        const int j4 = 320 + t + i * THREADS;
        if (j4 < 640) {
            const float ctr = __ldg(xrow + (j4 / 5 - CH));   // L1-hit broadcast
            __stcs(&outp[j4], make_float4(ctr, ctr, ctr, ctr));
        }
    }

    // --- commit pre-subtracted edge values to smem ---
    #pragma unroll
    for (int i = 0; i < 10; i++)
        s_nbr[half * 10 + i][c] = g[i] - ctr_c;
    __syncthreads();

    // --- edge half: out[c2][k] = s_nbr[k][c2]; j4 in [0,320) ---
    #pragma unroll
    for (int i = 0; i < 3; i++) {
        const int j4 = t + i * THREADS;
        if (j4 < 320) {
            const int c2 = j4 / 5;
            const int kk = (j4 - c2 * 5) * 4;
            float4 v;
            v.x = s_nbr[kk + 0][c2];
            v.y = s_nbr[kk + 1][c2];
            v.z = s_nbr[kk + 2][c2];
            v.w = s_nbr[kk + 3][c2];
            __stcs(&outp[j4], v);
        }
    }
}

extern "C" void kernel_launch(void* const* d_in, const int* in_sizes, int n_in,
                              void* d_out, int out_size) {
    const float* x   = (const float*)d_in[0];
    const void*  idx = d_in[1];
    float*       out = (float*)d_out;

    detect_idx_dtype_kernel<<<1, 1>>>((const long long*)idx);
    edge_feature_kernel<<<BDIM * NPTS, THREADS>>>(x, idx, out);
}